// round 10
// baseline (speedup 1.0000x reference)
#include <cuda_runtime.h>
typedef unsigned int u32;

#define HH 4096
#define ROWF 12288
#define TPB 384
#define CH 256

// sigma=0.5 taps normalized over the full 25-tap window (= reference), radius 2
#define K0f 0.78657070f
#define K1f 0.10645078f
#define K2f 2.63866e-4f
#define DECAYf 0.60653065971263342f
#define OMDf   0.39346934028736658f
#define INV3f  0.33333322222f        // 1/(3 + 1e-6)

__global__ __launch_bounds__(TPB, 4)
void chem_kernel(const float* __restrict__ D, const float* __restrict__ Cm,
                 float* __restrict__ out)
{
    __shared__ float stage[3264];          // 2 bufs x 4 rows x (<=408 floats)
    __shared__ float shI[4][TPB];

    const int tid  = threadIdx.x;
    const int c    = tid % 3;
    const int wb_  = tid - c;
    const int bx   = blockIdx.x;
    const bool wide = bx < 17;             // 17 strips of 128 cols + 20 of 96
    const int width = wide ? 128 : 96;
    const int w0    = wide ? (bx << 7) : (2176 + (bx - 17) * 96);
    const int NV    = wide ? 102 : 78;     // float4 per staged row
    const int RS    = NV * 4;              // floats per staged row
    const int h0    = blockIdx.y * CH;
    const bool act  = tid < width * 3;

    const float cc0 = __ldg(Cm + 0 + c);
    const float cc1 = __ldg(Cm + 3 + c);
    const float cc2 = __ldg(Cm + 6 + c);

    // loader mapping: vec w of 4*NV -> (row w/NV, lane w%NV)
    const int  j0   = tid / NV;
    const int  v0   = tid - j0 * NV;
    const bool val0 = tid < 4 * NV;        // lane maps to a real staged vector
    const long g0   = (long)(w0 - 4) * 3 + 4 * v0;
    const bool cok0 = val0 && (g0 >= 0) && (g0 + 4 <= ROWF);

    const int  nsec = 4 * NV - TPB;        // 24 (wide) or negative (narrow)
    const bool sec  = tid < nsec;
    const int  w1   = TPB + tid;
    const int  j1   = sec ? w1 / NV : 0;
    const int  v1   = sec ? (w1 - j1 * NV) : 0;
    const long g1   = (long)(w0 - 4) * 3 + 4 * v1;
    const bool cok1 = sec && (g1 >= 0) && (g1 + 4 <= ROWF);

    const u32 sbase   = (u32)__cvta_generic_to_shared(stage);
    const u32 bufstep = (u32)(RS * 16);    // 4 rows * RS floats * 4B
    const u32 sA0 = sbase + (u32)((j0 * RS + 4 * v0) * 4);
    const u32 sA1 = sbase + (u32)((j1 * RS + 4 * v1) * 4);

    float hb[8] = {0,0,0,0,0,0,0,0};
    float dr[4] = {0,0,0,0}, sr[4] = {0,0,0,0}, ds[4];
    float siir = 0.f;

    int rb = h0 - 30;                       // 72 batches of 4 rows; emit from b=8
    float* op = out + (long)(rb - 2) * ROWF + w0 * 3 + tid;

// NOTE: the cp.async for lane-set 0 MUST be predicated on val0 — a cp.async
// with src-size 0 still ZERO-FILLS its smem destination, and for tid >= 4*NV
// (narrow strips) that destination aliases buffer 1's rows.
#define ISSUE(RB, BUF) { \
    if (val0) { \
        const int  row = (RB) + j0; \
        const int  sz  = (cok0 && row >= 0 && row < HH) ? 16 : 0; \
        const float* gp = sz ? (D + (long)row * ROWF + g0) : D; \
        asm volatile("cp.async.cg.shared.global [%0], [%1], 16, %2;\n" \
                     :: "r"(sA0 + (u32)(BUF) * bufstep), "l"(gp), "r"(sz) : "memory"); \
    } \
    if (sec) { \
        const int  row1 = (RB) + j1; \
        const int  sz1  = (cok1 && row1 >= 0 && row1 < HH) ? 16 : 0; \
        const float* gp1 = sz1 ? (D + (long)row1 * ROWF + g1) : D; \
        asm volatile("cp.async.cg.shared.global [%0], [%1], 16, %2;\n" \
                     :: "r"(sA1 + (u32)(BUF) * bufstep), "l"(gp1), "r"(sz1) : "memory"); \
    } \
    asm volatile("cp.async.commit_group;\n" ::: "memory"); }

// Row r committed at phase S; output row ro = r-2. hb[(S-k)&7] holds row r-k.
#define ROWCOMP(S, J) { \
    const float* bp = stgf + (J) * RS; \
    const float xm2 = bp[tid+6],  xm1 = bp[tid+9]; \
    const float x0  = bp[tid+12]; \
    const float xp1 = bp[tid+15], xp2 = bp[tid+18]; \
    float hbv = x0 * K0f; \
    hbv = fmaf(xm1 + xp1, K1f, hbv); \
    hbv = fmaf(xm2 + xp2, K2f, hbv); \
    siir = fmaf(DECAYf, siir, x0); \
    hb[(S)&7] = hbv; \
    float vb = hb[((S)+6)&7] * K0f; \
    vb = fmaf(hb[((S)+7)&7] + hb[((S)+5)&7], K1f, vb); \
    vb = fmaf(hb[(S)&7]     + hb[((S)+4)&7], K2f, vb); \
    const float d_o = dr[((S)+2)&3]; \
    const float s_o = sr[((S)+2)&3]; \
    ds[J] = d_o; \
    shI[J][tid] = s_o + (d_o * INV3f) * (vb - s_o); \
    dr[(S)&3] = x0; \
    sr[(S)&3] = OMDf * siir; }

#define MIX(J) { \
    const float i0 = shI[J][wb_], i1 = shI[J][wb_+1], i2 = shI[J][wb_+2]; \
    const float inh = cc0*i0 + cc1*i1 + cc2*i2; \
    const float arg = (ds[J] - inh) * INV3f; \
    float t; asm("tanh.approx.f32 %0, %1;" : "=f"(t) : "f"(arg)); \
    op[(J)*ROWF] = 3.0f * t; }

#define CPWAIT(N) asm volatile("cp.async.wait_group " #N ";\n" ::: "memory")

#define SUPER(S0, BUF, EMIT, WAITN, ISS) { \
    CPWAIT(WAITN); \
    __syncthreads();                 /* stage batch visible */ \
    const float* stgf = stage + (BUF) * 4 * RS; \
    ROWCOMP((S0)+0, 0) ROWCOMP((S0)+1, 1) \
    ROWCOMP((S0)+2, 2) ROWCOMP((S0)+3, 3) \
    __syncthreads();                 /* stage reads done, shI visible */ \
    if (ISS) ISSUE(rb + 8, BUF) \
    if (EMIT && act) { MIX(0) MIX(1) MIX(2) MIX(3) } \
    rb += 4; op += 4 * (long)ROWF; }

    // prologue: batches 0,1 in flight
    ISSUE(rb,     0)
    ISSUE(rb + 4, 1)

    // warm-up: batches 0..7 (rows h0-30 .. h0+1, no emission)
#pragma unroll 1
    for (int p = 0; p < 4; ++p) { SUPER(0, 0, 0, 1, 1) SUPER(4, 1, 0, 1, 1) }

    // emit: batches 8..69 (rows h0 .. h0+247)
#pragma unroll 1
    for (int p = 0; p < 31; ++p) { SUPER(0, 0, 1, 1, 1) SUPER(4, 1, 1, 1, 1) }

    // tail: batches 70,71 (rows h0+248 .. h0+255) — no further issues
    SUPER(0, 0, 1, 1, 0)
    SUPER(4, 1, 1, 0, 0)

#undef SUPER
#undef CPWAIT
#undef MIX
#undef ROWCOMP
#undef ISSUE
}

extern "C" void kernel_launch(void* const* d_in, const int* in_sizes, int n_in,
                              void* d_out, int out_size)
{
    const float* D   = (const float*)d_in[0];   // (4096, 4096, 3) f32
    const float* Cm  = (const float*)d_in[1];   // (3, 3) f32
    float*       out = (float*)d_out;           // (4096, 4096, 3) f32
    dim3 grid(37, 16);                          // 592 blocks = 148 SMs * 4
    chem_kernel<<<grid, TPB>>>(D, Cm, out);
}

// round 11
// speedup vs baseline: 1.3204x; 1.3204x over previous
#include <cuda_runtime.h>
typedef unsigned int u32;

#define HH 4096
#define ROWF 12288          // floats per image row
#define TPB 384             // one thread per (col, chan)
#define RVEC 102            // float4 per staged row (128 + 8 halo cols)
#define RSTRIDE 408         // floats per staged row
#define BUFFLOATS 1632      // 4 rows * 408
#define BUFBYTES 6528

// horizontal taps: radius-1, renormalized so applied mass = 1 (zero-mean error)
#define KH0 0.78698593f
#define KH1 0.10650699f
// vertical taps: radius-2, reference-normalized values
#define K0f 0.78657070f
#define K1f 0.10645078f
#define K2f 2.63866e-4f
#define DECAYf 0.60653065971263342f
#define OMDf   0.39346934028736658f
#define INV3f  0.33333322222f        // 1/(3 + 1e-6)

__global__ __launch_bounds__(TPB, 4)
void chem_kernel(const float* __restrict__ D, const float* __restrict__ Cm,
                 float* __restrict__ out)
{
    __shared__ float stage[4 * BUFFLOATS];   // 26112 B, 4-deep stage rotation
    __shared__ float shI[2][4][TPB];         // 12288 B, batch-parity double buffer

    const int tid = threadIdx.x;
    const int c   = tid % 3;
    const int wb_ = tid - c;
    const int w0  = blockIdx.x << 7;         // 32 strips of 128 cols
    const int h0  = blockIdx.y << 8;         // 16 chunks of 256 rows

    const float cc0 = __ldg(Cm + 0 + c);
    const float cc1 = __ldg(Cm + 3 + c);
    const float cc2 = __ldg(Cm + 6 + c);

    // cp.async loader: vec v of 408 -> (row v/102, lane v%102); all 384 tids valid
    const int  j0     = tid / RVEC;
    const int  v0     = tid - j0 * RVEC;
    const long g0     = (long)(w0 - 4) * 3 + 4 * v0;
    const bool cok0   = (g0 >= 0) && (g0 + 4 <= ROWF);
    const bool sec    = tid < 24;                         // vecs 384..407 (row 3)
    const long g1     = (long)(w0 - 4) * 3 + 4 * (78 + tid);
    const bool cok1   = sec && (g1 >= 0) && (g1 + 4 <= ROWF);

    const u32 sb  = (u32)__cvta_generic_to_shared(stage);
    const u32 sA0 = sb + (u32)((j0 * RSTRIDE + 4 * v0) * 4);
    const u32 sA1 = sb + (u32)((3 * RSTRIDE + 4 * (78 + tid)) * 4);

    float hb[8] = {0,0,0,0,0,0,0,0};   // horizontal-blur ring
    float dr[4] = {0,0,0,0};           // raw density ring (lag 2)
    float sr[4] = {0,0,0,0};           // soft-cloud ring (lag 2)
    float ds[2][4];                    // density stash, batch-parity buffered
    float siir = 0.f;

    int rb = h0 - 26;                  // 71 batches of 4 rows (h0-26 .. h0+257)
    float* op = out + (long)(h0 - 32) * ROWF + w0 * 3 + tid;  // MIX lags 1 batch

#define ISSUE(RB, SBUF) { \
    const int  row = (RB) + j0; \
    const int  sz  = (cok0 && row >= 0 && row < HH) ? 16 : 0; \
    const float* gp = sz ? (D + (long)row * ROWF + g0) : D; \
    asm volatile("cp.async.cg.shared.global [%0], [%1], 16, %2;\n" \
                 :: "r"(sA0 + (u32)(SBUF) * BUFBYTES), "l"(gp), "r"(sz) : "memory"); \
    if (sec) { \
        const int  row1 = (RB) + 3; \
        const int  sz1  = (cok1 && row1 >= 0 && row1 < HH) ? 16 : 0; \
        const float* gp1 = sz1 ? (D + (long)row1 * ROWF + g1) : D; \
        asm volatile("cp.async.cg.shared.global [%0], [%1], 16, %2;\n" \
                     :: "r"(sA1 + (u32)(SBUF) * BUFBYTES), "l"(gp1), "r"(sz1) : "memory"); \
    } \
    asm volatile("cp.async.commit_group;\n" ::: "memory"); }

// warm row: horizontal blur + IIR + rings only
#define ROWW(S, J) { \
    const float* bp = stgf + (J) * RSTRIDE; \
    const float xm1 = bp[tid+9], x0 = bp[tid+12], xp1 = bp[tid+15]; \
    siir = fmaf(DECAYf, siir, x0); \
    hb[(S)&7] = fmaf(xm1 + xp1, KH1, x0 * KH0); \
    dr[(S)&3] = x0; \
    sr[(S)&3] = OMDf * siir; }

// emit row: + vertical blur (radius 2), mask blend, shI/ds stash (ro = r-2)
#define ROWE(S, J, PH) { \
    const float* bp = stgf + (J) * RSTRIDE; \
    const float xm1 = bp[tid+9], x0 = bp[tid+12], xp1 = bp[tid+15]; \
    siir = fmaf(DECAYf, siir, x0); \
    hb[(S)&7] = fmaf(xm1 + xp1, KH1, x0 * KH0); \
    float vb = hb[((S)+6)&7] * K0f; \
    vb = fmaf(hb[((S)+5)&7] + hb[((S)+7)&7], K1f, vb); \
    vb = fmaf(hb[((S)+4)&7] + hb[(S)&7],     K2f, vb); \
    const float d_o = dr[((S)+2)&3]; \
    const float s_o = sr[((S)+2)&3]; \
    ds[PH][J] = d_o; \
    shI[PH][J][tid] = s_o + (d_o * INV3f) * (vb - s_o); \
    dr[(S)&3] = x0; \
    sr[(S)&3] = OMDf * siir; }

#define MIX1(PB, J) { \
    const float i0 = shI[PB][J][wb_], i1 = shI[PB][J][wb_+1], i2 = shI[PB][J][wb_+2]; \
    const float inh = cc0*i0 + cc1*i1 + cc2*i2; \
    const float arg = (ds[PB][J] - inh) * INV3f; \
    float t; asm("tanh.approx.f32 %0, %1;" : "=f"(t) : "f"(arg)); \
    op[(J) * (long)ROWF] = 3.0f * t; }

#define MIXB(PB) { MIX1(PB,0) MIX1(PB,1) MIX1(PB,2) MIX1(PB,3) }

#define CPWAIT(N) asm volatile("cp.async.wait_group " #N ";\n" ::: "memory")

// ONE barrier per batch. Stage buf (SB+2)&3 was fully read before barrier(k-1),
// so refilling it after barrier(k) is race-free. shI/ds ping-pong by parity.
#define BWARM(SB, S0, WN) { \
    CPWAIT(WN); __syncthreads(); \
    ISSUE(rb + 8, ((SB)+2)&3) \
    const float* stgf = stage + (SB) * BUFFLOATS; \
    ROWW((S0)+0,0) ROWW((S0)+1,1) ROWW((S0)+2,2) ROWW((S0)+3,3) \
    rb += 4; op += 4 * (long)ROWF; }

#define BEMIT(SB, S0, PH, DOMIX, DOISS, WN) { \
    CPWAIT(WN); __syncthreads(); \
    if (DOISS) ISSUE(rb + 8, ((SB)+2)&3) \
    if (DOMIX) { MIXB((PH)^1) } \
    const float* stgf = stage + (SB) * BUFFLOATS; \
    ROWE((S0)+0,0,PH) ROWE((S0)+1,1,PH) ROWE((S0)+2,2,PH) ROWE((S0)+3,3,PH) \
    rb += 4; op += 4 * (long)ROWF; }

    // prologue: batches 0,1 in flight (depth 2 = 8-row slack)
    ISSUE(rb,     0)
    ISSUE(rb + 4, 1)

    // warm-up: batches 0..6 (rows h0-26 .. h0+1)
    BWARM(0,0,1) BWARM(1,4,1) BWARM(2,0,1) BWARM(3,4,1)
    BWARM(0,0,1) BWARM(1,4,1) BWARM(2,0,1)

    // k=7: first shI batch (computes ro = h0..h0+3), no MIX yet
    BEMIT(3,4,1, 0,1,1)

    // k=8..67: steady state (MIX batch k-1, compute batch k)
#pragma unroll 1
    for (int p = 0; p < 15; ++p) {
        BEMIT(0,0,0, 1,1,1) BEMIT(1,4,1, 1,1,1)
        BEMIT(2,0,0, 1,1,1) BEMIT(3,4,1, 1,1,1)
    }

    // k=68 (last ISSUE: batch 70), k=69, k=70
    BEMIT(0,0,0, 1,1,1)
    BEMIT(1,4,1, 1,0,1)
    BEMIT(2,0,0, 1,0,0)

    // epilogue: store batch 70's rows (h0+252 .. h0+255)
    __syncthreads();
    MIXB(0)

#undef BWARM
#undef BEMIT
#undef CPWAIT
#undef MIXB
#undef MIX1
#undef ROWE
#undef ROWW
#undef ISSUE
}

extern "C" void kernel_launch(void* const* d_in, const int* in_sizes, int n_in,
                              void* d_out, int out_size)
{
    const float* D   = (const float*)d_in[0];   // (4096, 4096, 3) f32
    const float* Cm  = (const float*)d_in[1];   // (3, 3) f32
    float*       out = (float*)d_out;           // (4096, 4096, 3) f32
    dim3 grid(32, 16);                          // 512 blocks, uniform 128-col strips
    chem_kernel<<<grid, TPB>>>(D, Cm, out);
}